// round 1
// baseline (speedup 1.0000x reference)
#include <cuda_runtime.h>
#include <math.h>

#define NN 100000
#define NE 1600000
#define NC 2000
#define NF 64
#define EFD 41
#define HF 128
#define DIN 169

typedef unsigned long long ull;

// ---------------- scratch (static __device__, no allocations) ----------------
__device__ float g_X[NN * NF];          // node features          25.6 MB
__device__ float g_P1[NN * HF];         // X @ Wf[rows 0:64]      51.2 MB
__device__ float g_P2[NN * HF];         // X @ Wf[rows 64:128]    51.2 MB
__device__ float g_Z[204800000];        // z pre-BN, [E,128]     819.2 MB
__device__ float g_ACC[NN * NF];        // per-node msg sums      25.6 MB
__device__ int   g_DEG[NN];
__device__ int   g_CNT[NC];
__device__ float g_CRY[NC * NF];
__device__ double g_S[2 * HF];          // edge BN sum / sumsq
__device__ double g_NS[2 * NF];         // node BN sum / sumsq
__device__ float g_AF[2 * HF];          // edge BN scale/shift
__device__ float g_NAF[2 * NF];         // node BN scale/shift

// ---------------- helpers ----------------
__device__ __forceinline__ ull pack2(float x) {
    ull r; asm("mov.b64 %0, {%1, %1};" : "=l"(r) : "f"(x)); return r;
}
__device__ __forceinline__ ull packf2(float x, float y) {
    ull r; asm("mov.b64 %0, {%1, %2};" : "=l"(r) : "f"(x), "f"(y)); return r;
}
__device__ __forceinline__ void ffma2(ull& d, ull a, ull b) {
    asm("fma.rn.f32x2 %0, %1, %2, %0;" : "+l"(d) : "l"(a), "l"(b));
}
__device__ __forceinline__ float2 unpk(ull v) {
    float2 r; asm("mov.b64 {%0, %1}, %2;" : "=f"(r.x), "=f"(r.y) : "l"(v)); return r;
}
__device__ __forceinline__ float sp_f(float x) {   // softplus = logaddexp(x,0)
    return fmaxf(x, 0.f) + log1pf(expf(-fabsf(x)));
}
__device__ __forceinline__ float sig_f(float x) {
    return 1.f / (1.f + expf(-x));
}

// ---------------- setup kernels ----------------
__global__ void k_pre() {
    int i = blockIdx.x * 256 + threadIdx.x;
    if (i < NN) g_DEG[i] = 0;
    if (i < NC) g_CNT[i] = 0;
    if (i < NC * NF) g_CRY[i] = 0.f;
}

__global__ void k_embed(const int* __restrict__ nf, const float* __restrict__ emb) {
    int i = blockIdx.x * 256 + threadIdx.x;       // NN*16 threads
    if (i >= NN * 16) return;
    int n = i >> 4, c = i & 15;
    int v = nf[n];
    float4 val = ((const float4*)(emb + (size_t)v * NF))[c];
    ((float4*)(g_X + (size_t)n * NF))[c] = val;
}

__global__ void k_deg(const int* __restrict__ idx1) {
    int e = blockIdx.x * 256 + threadIdx.x;
    if (e < NE) atomicAdd(&g_DEG[idx1[e]], 1);
}

__global__ void k_cnt3(const int* __restrict__ idx3) {
    int n = blockIdx.x * 256 + threadIdx.x;
    if (n < NN) atomicAdd(&g_CNT[idx3[n]], 1);
}

__global__ void k_zero_layer() {
    for (int i = blockIdx.x * 256 + threadIdx.x; i < NN * NF; i += gridDim.x * 256) {
        g_ACC[i] = 0.f;
        if (i < 2 * HF) g_S[i] = 0.0;
        if (i < 2 * NF) g_NS[i] = 0.0;
    }
}

// ---------------- node GEMM: P1/P2 = X @ Wf[l][half*64 : half*64+64] ----------------
// tile 64 nodes x 128 feats, K=64. thread: 4 nodes x 8 feats via f32x2
__global__ __launch_bounds__(256) void k_nodegemm(const float* __restrict__ Wf, int layer) {
    __shared__ float sW[64 * HF];   // 32 KB
    __shared__ float sX[64 * NF];   // 16 KB
    const float* Wb = Wf + ((size_t)layer * DIN + blockIdx.y * 64) * HF;
    int tid = threadIdx.x;
    #pragma unroll 4
    for (int i = tid; i < 64 * HF; i += 256) sW[i] = Wb[i];
    int n0 = blockIdx.x * 64;
    for (int i = tid; i < 64 * NF; i += 256) {
        int r = i >> 6, c = i & 63, n = n0 + r;
        sX[i] = (n < NN) ? g_X[(size_t)n * NF + c] : 0.f;
    }
    __syncthreads();
    int fg = tid & 15, eg = tid >> 4;
    int fa = fg * 4, fb = 64 + fg * 4;
    ull acc[4][4];
    #pragma unroll
    for (int j = 0; j < 4; j++)
        #pragma unroll
        for (int q = 0; q < 4; q++) acc[j][q] = 0ULL;
    #pragma unroll 1
    for (int k = 0; k < 64; k++) {
        const ull* wa = (const ull*)(sW + k * HF + fa);
        const ull* wb = (const ull*)(sW + k * HF + fb);
        ull w0 = wa[0], w1 = wa[1], w2 = wb[0], w3 = wb[1];
        #pragma unroll
        for (int j = 0; j < 4; j++) {
            ull a = pack2(sX[(eg * 4 + j) * NF + k]);
            ffma2(acc[j][0], a, w0); ffma2(acc[j][1], a, w1);
            ffma2(acc[j][2], a, w2); ffma2(acc[j][3], a, w3);
        }
    }
    float* out = blockIdx.y ? g_P2 : g_P1;
    #pragma unroll
    for (int j = 0; j < 4; j++) {
        int n = n0 + eg * 4 + j;
        if (n < NN) {
            float2 v0 = unpk(acc[j][0]), v1 = unpk(acc[j][1]);
            float2 v2 = unpk(acc[j][2]), v3 = unpk(acc[j][3]);
            *(float4*)(out + (size_t)n * HF + fa) = make_float4(v0.x, v0.y, v1.x, v1.y);
            *(float4*)(out + (size_t)n * HF + fb) = make_float4(v2.x, v2.y, v3.x, v3.y);
        }
    }
}

// ---------------- edge pass 1: z = P1[i1] + P2[i2] + ef @ Wf_e + bf; write Z; BN stats ----
// tile 128 edges x 128 feats, K=41. thread: 8 edges x 8 feats via f32x2
__global__ __launch_bounds__(256) void k_edge1(
    const float* __restrict__ ef, const int* __restrict__ idx1, const int* __restrict__ idx2,
    const float* __restrict__ Wf, const float* __restrict__ bfp, int layer)
{
    __shared__ float sW[EFD * HF];     // 41*128*4 = 21.0 KB
    __shared__ float sE[128 * 42];     // 21.5 KB
    __shared__ float sS1[HF], sS2[HF];
    const float* Wb = Wf + ((size_t)layer * DIN + 128) * HF;
    int tid = threadIdx.x;
    for (int i = tid; i < EFD * HF; i += 256) sW[i] = Wb[i];
    size_t e0 = (size_t)blockIdx.x * 128;
    const float* efb = ef + e0 * EFD;
    for (int i = tid; i < 128 * EFD; i += 256) sE[(i / EFD) * 42 + (i % EFD)] = efb[i];
    if (tid < HF) { sS1[tid] = 0.f; sS2[tid] = 0.f; }
    __syncthreads();

    int fg = tid & 15, eg = tid >> 4;
    int fa = fg * 4, fb = 64 + fg * 4;
    const float* bfl = bfp + layer * HF;
    float4 bva = *(const float4*)(bfl + fa);
    float4 bvb = *(const float4*)(bfl + fb);

    ull acc[8][4];
    #pragma unroll
    for (int j = 0; j < 8; j++) {
        int e = eg * 8 + j;
        int i1 = idx1[e0 + e], i2 = idx2[e0 + e];
        float4 p1a = *(const float4*)(g_P1 + (size_t)i1 * HF + fa);
        float4 p1b = *(const float4*)(g_P1 + (size_t)i1 * HF + fb);
        float4 p2a = *(const float4*)(g_P2 + (size_t)i2 * HF + fa);
        float4 p2b = *(const float4*)(g_P2 + (size_t)i2 * HF + fb);
        acc[j][0] = packf2(p1a.x + p2a.x + bva.x, p1a.y + p2a.y + bva.y);
        acc[j][1] = packf2(p1a.z + p2a.z + bva.z, p1a.w + p2a.w + bva.w);
        acc[j][2] = packf2(p1b.x + p2b.x + bvb.x, p1b.y + p2b.y + bvb.y);
        acc[j][3] = packf2(p1b.z + p2b.z + bvb.z, p1b.w + p2b.w + bvb.w);
    }
    #pragma unroll 1
    for (int k = 0; k < EFD; k++) {
        const ull* wa = (const ull*)(sW + k * HF + fa);
        const ull* wb = (const ull*)(sW + k * HF + fb);
        ull w0 = wa[0], w1 = wa[1], w2 = wb[0], w3 = wb[1];
        #pragma unroll
        for (int j = 0; j < 8; j++) {
            ull a = pack2(sE[(eg * 8 + j) * 42 + k]);
            ffma2(acc[j][0], a, w0); ffma2(acc[j][1], a, w1);
            ffma2(acc[j][2], a, w2); ffma2(acc[j][3], a, w3);
        }
    }
    float s1[8] = {0,0,0,0,0,0,0,0}, s2[8] = {0,0,0,0,0,0,0,0};
    #pragma unroll
    for (int j = 0; j < 8; j++) {
        int e = eg * 8 + j;
        float2 v0 = unpk(acc[j][0]), v1 = unpk(acc[j][1]);
        float2 v2 = unpk(acc[j][2]), v3 = unpk(acc[j][3]);
        float* zr = g_Z + (e0 + e) * HF;
        *(float4*)(zr + fa) = make_float4(v0.x, v0.y, v1.x, v1.y);
        *(float4*)(zr + fb) = make_float4(v2.x, v2.y, v3.x, v3.y);
        s1[0] += v0.x; s2[0] += v0.x * v0.x;
        s1[1] += v0.y; s2[1] += v0.y * v0.y;
        s1[2] += v1.x; s2[2] += v1.x * v1.x;
        s1[3] += v1.y; s2[3] += v1.y * v1.y;
        s1[4] += v2.x; s2[4] += v2.x * v2.x;
        s1[5] += v2.y; s2[5] += v2.y * v2.y;
        s1[6] += v3.x; s2[6] += v3.x * v3.x;
        s1[7] += v3.y; s2[7] += v3.y * v3.y;
    }
    #pragma unroll
    for (int q = 0; q < 4; q++) {
        atomicAdd(&sS1[fa + q], s1[q]);     atomicAdd(&sS2[fa + q], s2[q]);
        atomicAdd(&sS1[fb + q], s1[4 + q]); atomicAdd(&sS2[fb + q], s2[4 + q]);
    }
    __syncthreads();
    if (tid < HF) {
        atomicAdd(&g_S[tid], (double)sS1[tid]);
        atomicAdd(&g_S[HF + tid], (double)sS2[tid]);
    }
}

__global__ void k_efin(const float* __restrict__ g1, const float* __restrict__ be1, int layer) {
    int f = threadIdx.x;  // 128
    double mean = g_S[f] / (double)NE;
    double var  = g_S[HF + f] / (double)NE - mean * mean;
    float istd = (float)rsqrt(var + 1e-5);
    float sc = g1[layer * HF + f] * istd;
    g_AF[f] = sc;
    g_AF[HF + f] = be1[layer * HF + f] - (float)mean * sc;
}

// ---------------- edge pass 2: BN, gate*softplus, scatter to nodes ----------------
__global__ void k_edge2(const int* __restrict__ idx1) {
    int gid = blockIdx.x * 256 + threadIdx.x;     // NE*64 threads exactly
    int e = gid >> 6, f = gid & 63;
    const float* zr = g_Z + (size_t)e * HF;
    float a = zr[f]      * g_AF[f]      + g_AF[HF + f];
    float b = zr[NF + f] * g_AF[NF + f] + g_AF[HF + NF + f];
    float m = sig_f(a) * sp_f(b);
    atomicAdd(&g_ACC[(size_t)idx1[e] * NF + f], m);
}

// ---------------- node BN stats + apply ----------------
__global__ void k_nstats() {
    __shared__ float s1[NF], s2[NF];
    int tid = threadIdx.x;
    if (tid < NF) { s1[tid] = 0.f; s2[tid] = 0.f; }
    __syncthreads();
    float a1 = 0.f, a2 = 0.f;
    int f = tid & 63;
    for (int i = blockIdx.x * 256 + tid; i < NN * NF; i += gridDim.x * 256) {
        int n = i >> 6;
        float nm = g_ACC[i] / (float)max(g_DEG[n], 1);
        a1 += nm; a2 += nm * nm;
    }
    atomicAdd(&s1[f], a1); atomicAdd(&s2[f], a2);
    __syncthreads();
    if (tid < NF) {
        atomicAdd(&g_NS[tid], (double)s1[tid]);
        atomicAdd(&g_NS[NF + tid], (double)s2[tid]);
    }
}

__global__ void k_nfin(const float* __restrict__ g2, const float* __restrict__ be2, int layer) {
    int f = threadIdx.x;  // 64
    double mean = g_NS[f] / (double)NN;
    double var  = g_NS[NF + f] / (double)NN - mean * mean;
    float istd = (float)rsqrt(var + 1e-5);
    float sc = g2[layer * NF + f] * istd;
    g_NAF[f] = sc;
    g_NAF[NF + f] = be2[layer * NF + f] - (float)mean * sc;
}

__global__ void k_napply() {
    for (int i = blockIdx.x * 256 + threadIdx.x; i < NN * NF; i += gridDim.x * 256) {
        int f = i & 63, n = i >> 6;
        float nm = g_ACC[i] / (float)max(g_DEG[n], 1);
        float v = g_X[i] + nm * g_NAF[f] + g_NAF[NF + f];
        g_X[i] = sp_f(v);
    }
}

// ---------------- readout ----------------
__global__ void k_cryacc(const int* __restrict__ idx3) {
    int i = blockIdx.x * 256 + threadIdx.x;   // NN*NF exactly
    int n = i >> 6, f = i & 63;
    atomicAdd(&g_CRY[idx3[n] * NF + f], g_X[i]);
}

__global__ void k_head(const float* __restrict__ Wc, const float* __restrict__ bc,
                       const float* __restrict__ Wo, const float* __restrict__ bo,
                       float* __restrict__ out) {
    __shared__ float c[NF];
    __shared__ float r0s[4], r1s[4];
    int cid = blockIdx.x, tid = threadIdx.x;   // 128 threads
    if (tid < NF) {
        int cnt = g_CNT[cid];
        c[tid] = g_CRY[cid * NF + tid] / (float)max(cnt, 1);
    }
    __syncthreads();
    float acc = bc[tid];
    #pragma unroll
    for (int k = 0; k < NF; k++) acc += c[k] * Wc[k * HF + tid];
    float h = sp_f(acc);
    float o0 = h * Wo[tid * 2], o1 = h * Wo[tid * 2 + 1];
    #pragma unroll
    for (int s = 16; s; s >>= 1) {
        o0 += __shfl_down_sync(0xffffffffu, o0, s);
        o1 += __shfl_down_sync(0xffffffffu, o1, s);
    }
    if ((tid & 31) == 0) { r0s[tid >> 5] = o0; r1s[tid >> 5] = o1; }
    __syncthreads();
    if (tid == 0) {
        out[cid * 2]     = r0s[0] + r0s[1] + r0s[2] + r0s[3] + bo[0];
        out[cid * 2 + 1] = r1s[0] + r1s[1] + r1s[2] + r1s[3] + bo[1];
    }
}

// ---------------- launch ----------------
extern "C" void kernel_launch(void* const* d_in, const int* in_sizes, int n_in,
                              void* d_out, int out_size) {
    const int*   node_fea = (const int*)  d_in[0];
    const float* edge_fea = (const float*)d_in[1];
    const int*   idx1     = (const int*)  d_in[2];
    const int*   idx2     = (const int*)  d_in[3];
    const int*   idx3     = (const int*)  d_in[4];
    const float* emb      = (const float*)d_in[5];
    const float* Wf       = (const float*)d_in[6];
    const float* bf       = (const float*)d_in[7];
    const float* g1       = (const float*)d_in[8];
    const float* be1      = (const float*)d_in[9];
    const float* g2       = (const float*)d_in[10];
    const float* be2      = (const float*)d_in[11];
    const float* Wc       = (const float*)d_in[12];
    const float* bc       = (const float*)d_in[13];
    const float* Wo       = (const float*)d_in[14];
    const float* bo       = (const float*)d_in[15];
    float* out = (float*)d_out;

    k_pre<<<500, 256>>>();
    k_embed<<<6250, 256>>>(node_fea, emb);
    k_deg<<<6250, 256>>>(idx1);
    k_cnt3<<<391, 256>>>(idx3);
    for (int l = 0; l < 3; l++) {
        k_zero_layer<<<2048, 256>>>();
        dim3 gg(1563, 2);
        k_nodegemm<<<gg, 256>>>(Wf, l);
        k_edge1<<<12500, 256>>>(edge_fea, idx1, idx2, Wf, bf, l);
        k_efin<<<1, 128>>>(g1, be1, l);
        k_edge2<<<400000, 256>>>(idx1);
        k_nstats<<<1024, 256>>>();
        k_nfin<<<1, 64>>>(g2, be2, l);
        k_napply<<<2048, 256>>>();
    }
    k_cryacc<<<25000, 256>>>(idx3);
    k_head<<<2000, 128>>>(Wc, bc, Wo, bo, out);
}

// round 2
// speedup vs baseline: 1.0508x; 1.0508x over previous
#include <cuda_runtime.h>
#include <cuda_fp16.h>
#include <math.h>

#define NN 100000
#define NE 1600000
#define NC 2000
#define NF 64
#define EFD 41
#define HF 128
#define DIN 169

typedef unsigned long long ull;

// ---------------- scratch (static __device__, no allocations) ----------------
__device__ float   g_X[NN * NF];           // node features
__device__ float   g_P1[NN * HF];          // X @ Wf[rows 0:64]
__device__ float   g_P2[NN * HF];          // X @ Wf[rows 64:128]
__device__ __half2 g_Zh[(size_t)NE * 64];  // z pre-BN packed (gate_f, conv_f)  409.6MB
__device__ float   g_ACC[NN * NF];         // per-node msg means
__device__ int     g_DEG[NN];
__device__ int     g_CNT[NC];
__device__ float   g_CRY[NC * NF];
__device__ double  g_S[2 * HF];            // edge BN sum / sumsq
__device__ double  g_NS[2 * NF];           // node BN sum / sumsq
__device__ float   g_AF[2 * HF];           // edge BN scale/shift
__device__ float   g_NAF[2 * NF];          // node BN scale/shift
// counting-sort infra
__device__ int g_TMP[NN];                  // in-block exclusive scan of deg
__device__ int g_BS[512];                  // per-block sums
__device__ int g_BSX[512];                 // exclusive scan of block sums
__device__ int g_START[NN];
__device__ int g_CUR[NN];
__device__ int g_ESRC[NE];                 // sorted position -> original edge id

// ---------------- helpers ----------------
__device__ __forceinline__ ull pack2(float x) {
    ull r; asm("mov.b64 %0, {%1, %1};" : "=l"(r) : "f"(x)); return r;
}
__device__ __forceinline__ ull packf2(float x, float y) {
    ull r; asm("mov.b64 %0, {%1, %2};" : "=l"(r) : "f"(x), "f"(y)); return r;
}
__device__ __forceinline__ void ffma2(ull& d, ull a, ull b) {
    asm("fma.rn.f32x2 %0, %1, %2, %0;" : "+l"(d) : "l"(a), "l"(b));
}
__device__ __forceinline__ float2 unpk(ull v) {
    float2 r; asm("mov.b64 {%0, %1}, %2;" : "=f"(r.x), "=f"(r.y) : "l"(v)); return r;
}
__device__ __forceinline__ float sp_f(float x) {   // softplus (fast)
    return fmaxf(x, 0.f) + __logf(1.f + __expf(-fabsf(x)));
}
__device__ __forceinline__ float sig_f(float x) {
    return __fdividef(1.f, 1.f + __expf(-x));
}

// ---------------- setup kernels ----------------
__global__ void k_pre() {
    int i = blockIdx.x * 256 + threadIdx.x;
    if (i < NN) g_DEG[i] = 0;
    if (i < NC) g_CNT[i] = 0;
    if (i < NC * NF) g_CRY[i] = 0.f;
}

__global__ void k_embed(const int* __restrict__ nf, const float* __restrict__ emb) {
    int i = blockIdx.x * 256 + threadIdx.x;       // NN*16 threads
    if (i >= NN * 16) return;
    int n = i >> 4, c = i & 15;
    int v = nf[n];
    float4 val = ((const float4*)(emb + (size_t)v * NF))[c];
    ((float4*)(g_X + (size_t)n * NF))[c] = val;
}

__global__ void k_deg(const int* __restrict__ idx1) {
    int e = blockIdx.x * 256 + threadIdx.x;
    if (e < NE) atomicAdd(&g_DEG[idx1[e]], 1);
}

__global__ void k_cnt3(const int* __restrict__ idx3) {
    int n = blockIdx.x * 256 + threadIdx.x;
    if (n < NN) atomicAdd(&g_CNT[idx3[n]], 1);
}

// ---------------- counting sort (deg -> start offsets -> permutation) -------
__global__ void k_scan1() {
    __shared__ int s[256];
    int tid = threadIdx.x;
    int n = blockIdx.x * 256 + tid;
    int d = (n < NN) ? g_DEG[n] : 0;
    s[tid] = d;
    __syncthreads();
    for (int off = 1; off < 256; off <<= 1) {
        int v = (tid >= off) ? s[tid - off] : 0;
        __syncthreads();
        s[tid] += v;
        __syncthreads();
    }
    if (n < NN) g_TMP[n] = s[tid] - d;
    if (tid == 255) g_BS[blockIdx.x] = s[255];
}

__global__ void k_scan2() {
    __shared__ int s[512];
    int tid = threadIdx.x;
    int d = (tid < 391) ? g_BS[tid] : 0;
    s[tid] = d;
    __syncthreads();
    for (int off = 1; off < 512; off <<= 1) {
        int v = (tid >= off) ? s[tid - off] : 0;
        __syncthreads();
        s[tid] += v;
        __syncthreads();
    }
    if (tid < 391) g_BSX[tid] = s[tid] - d;
}

__global__ void k_scan3() {
    int n = blockIdx.x * 256 + threadIdx.x;
    if (n < NN) {
        int st = g_TMP[n] + g_BSX[blockIdx.x];
        g_START[n] = st;
        g_CUR[n] = st;
    }
}

__global__ void k_perm(const int* __restrict__ idx1) {
    int e = blockIdx.x * 256 + threadIdx.x;
    if (e < NE) {
        int pos = atomicAdd(&g_CUR[idx1[e]], 1);
        g_ESRC[pos] = e;
    }
}

__global__ void k_zstat() {
    int tid = threadIdx.x;  // 256
    g_S[tid] = 0.0;
    if (tid < 2 * NF) g_NS[tid] = 0.0;
}

// ---------------- node GEMM: P1/P2 = X @ Wf[l][half*64 : half*64+64] --------
__global__ __launch_bounds__(256) void k_nodegemm(const float* __restrict__ Wf, int layer) {
    __shared__ float sW[64 * HF];   // 32 KB
    __shared__ float sX[64 * NF];   // 16 KB
    const float* Wb = Wf + ((size_t)layer * DIN + blockIdx.y * 64) * HF;
    int tid = threadIdx.x;
    #pragma unroll 4
    for (int i = tid; i < 64 * HF; i += 256) sW[i] = Wb[i];
    int n0 = blockIdx.x * 64;
    for (int i = tid; i < 64 * NF; i += 256) {
        int r = i >> 6, c = i & 63, n = n0 + r;
        sX[i] = (n < NN) ? g_X[(size_t)n * NF + c] : 0.f;
    }
    __syncthreads();
    int fg = tid & 15, eg = tid >> 4;
    int fa = fg * 4, fb = 64 + fg * 4;
    ull acc[4][4];
    #pragma unroll
    for (int j = 0; j < 4; j++)
        #pragma unroll
        for (int q = 0; q < 4; q++) acc[j][q] = 0ULL;
    #pragma unroll 1
    for (int k = 0; k < 64; k++) {
        ulonglong2 wa = *(const ulonglong2*)(sW + k * HF + fa);
        ulonglong2 wb = *(const ulonglong2*)(sW + k * HF + fb);
        #pragma unroll
        for (int j = 0; j < 4; j++) {
            ull a = pack2(sX[(eg * 4 + j) * NF + k]);
            ffma2(acc[j][0], a, wa.x); ffma2(acc[j][1], a, wa.y);
            ffma2(acc[j][2], a, wb.x); ffma2(acc[j][3], a, wb.y);
        }
    }
    float* out = blockIdx.y ? g_P2 : g_P1;
    #pragma unroll
    for (int j = 0; j < 4; j++) {
        int n = n0 + eg * 4 + j;
        if (n < NN) {
            float2 v0 = unpk(acc[j][0]), v1 = unpk(acc[j][1]);
            float2 v2 = unpk(acc[j][2]), v3 = unpk(acc[j][3]);
            *(float4*)(out + (size_t)n * HF + fa) = make_float4(v0.x, v0.y, v1.x, v1.y);
            *(float4*)(out + (size_t)n * HF + fb) = make_float4(v2.x, v2.y, v3.x, v3.y);
        }
    }
}

// ---------------- edge pass 1 (sorted order): z -> Zh (fp16) + BN stats -----
// row p in Zh corresponds to sorted position p; edge id = g_ESRC[p]
__global__ __launch_bounds__(256) void k_edge1(
    const float* __restrict__ ef, const int* __restrict__ idx1, const int* __restrict__ idx2,
    const float* __restrict__ Wf, const float* __restrict__ bfp, int layer)
{
    __shared__ float sW[42 * HF];      // 21 KB (row 41 zeroed)
    __shared__ float sE[128 * 42];     // 21 KB (col 41 zeroed)
    __shared__ int sI1[128], sI2[128], sSRC[128];
    __shared__ float sS1[HF], sS2[HF];
    const float* Wb = Wf + ((size_t)layer * DIN + 128) * HF;
    int tid = threadIdx.x;
    for (int i = tid; i < 42 * HF; i += 256) sW[i] = (i < EFD * HF) ? Wb[i] : 0.f;
    size_t p0 = (size_t)blockIdx.x * 128;
    if (tid < 128) {
        int e = g_ESRC[p0 + tid];
        sSRC[tid] = e;
        sI1[tid] = idx1[e];
        sI2[tid] = idx2[e];
    }
    if (tid < HF) { sS1[tid] = 0.f; sS2[tid] = 0.f; }
    __syncthreads();
    for (int i = tid; i < 128 * 42; i += 256) {
        int r = i / 42, c = i - r * 42;
        sE[i] = (c < EFD) ? ef[(size_t)sSRC[r] * EFD + c] : 0.f;
    }

    int fg = tid & 15, eg = tid >> 4;
    int fa = fg * 4, fb = 64 + fg * 4;
    const float* bfl = bfp + layer * HF;
    float4 bva = *(const float4*)(bfl + fa);
    float4 bvb = *(const float4*)(bfl + fb);

    ull acc[8][4];
    #pragma unroll
    for (int j = 0; j < 8; j++) {
        int r = eg * 8 + j;
        int i1 = sI1[r], i2 = sI2[r];
        float4 p1a = *(const float4*)(g_P1 + (size_t)i1 * HF + fa);
        float4 p1b = *(const float4*)(g_P1 + (size_t)i1 * HF + fb);
        float4 p2a = *(const float4*)(g_P2 + (size_t)i2 * HF + fa);
        float4 p2b = *(const float4*)(g_P2 + (size_t)i2 * HF + fb);
        acc[j][0] = packf2(p1a.x + p2a.x + bva.x, p1a.y + p2a.y + bva.y);
        acc[j][1] = packf2(p1a.z + p2a.z + bva.z, p1a.w + p2a.w + bva.w);
        acc[j][2] = packf2(p1b.x + p2b.x + bvb.x, p1b.y + p2b.y + bvb.y);
        acc[j][3] = packf2(p1b.z + p2b.z + bvb.z, p1b.w + p2b.w + bvb.w);
    }
    __syncthreads();

    #pragma unroll 1
    for (int k = 0; k < 42; k += 2) {
        ulonglong2 wa0 = *(const ulonglong2*)(sW + k * HF + fa);
        ulonglong2 wb0 = *(const ulonglong2*)(sW + k * HF + fb);
        ulonglong2 wa1 = *(const ulonglong2*)(sW + (k + 1) * HF + fa);
        ulonglong2 wb1 = *(const ulonglong2*)(sW + (k + 1) * HF + fb);
        #pragma unroll
        for (int j = 0; j < 8; j++) {
            float2 av = *(const float2*)(sE + (eg * 8 + j) * 42 + k);
            ull a0 = pack2(av.x), a1 = pack2(av.y);
            ffma2(acc[j][0], a0, wa0.x); ffma2(acc[j][1], a0, wa0.y);
            ffma2(acc[j][2], a0, wb0.x); ffma2(acc[j][3], a0, wb0.y);
            ffma2(acc[j][0], a1, wa1.x); ffma2(acc[j][1], a1, wa1.y);
            ffma2(acc[j][2], a1, wb1.x); ffma2(acc[j][3], a1, wb1.y);
        }
    }

    float s1[8] = {0,0,0,0,0,0,0,0}, s2[8] = {0,0,0,0,0,0,0,0};
    #pragma unroll
    for (int j = 0; j < 8; j++) {
        size_t p = p0 + eg * 8 + j;
        float2 v0 = unpk(acc[j][0]), v1 = unpk(acc[j][1]);
        float2 v2 = unpk(acc[j][2]), v3 = unpk(acc[j][3]);
        // pack (gate_f, conv_f) pairs: feat fa+q pairs with 64+fa+q
        __half2 hp[4];
        hp[0] = __floats2half2_rn(v0.x, v2.x);
        hp[1] = __floats2half2_rn(v0.y, v2.y);
        hp[2] = __floats2half2_rn(v1.x, v3.x);
        hp[3] = __floats2half2_rn(v1.y, v3.y);
        *(uint4*)(g_Zh + p * 64 + fa) = *(uint4*)hp;
        s1[0] += v0.x; s2[0] += v0.x * v0.x;
        s1[1] += v0.y; s2[1] += v0.y * v0.y;
        s1[2] += v1.x; s2[2] += v1.x * v1.x;
        s1[3] += v1.y; s2[3] += v1.y * v1.y;
        s1[4] += v2.x; s2[4] += v2.x * v2.x;
        s1[5] += v2.y; s2[5] += v2.y * v2.y;
        s1[6] += v3.x; s2[6] += v3.x * v3.x;
        s1[7] += v3.y; s2[7] += v3.y * v3.y;
    }
    #pragma unroll
    for (int q = 0; q < 4; q++) {
        atomicAdd(&sS1[fa + q], s1[q]);     atomicAdd(&sS2[fa + q], s2[q]);
        atomicAdd(&sS1[fb + q], s1[4 + q]); atomicAdd(&sS2[fb + q], s2[4 + q]);
    }
    __syncthreads();
    if (tid < HF) {
        atomicAdd(&g_S[tid], (double)sS1[tid]);
        atomicAdd(&g_S[HF + tid], (double)sS2[tid]);
    }
}

__global__ void k_efin(const float* __restrict__ g1, const float* __restrict__ be1, int layer) {
    int f = threadIdx.x;  // 128
    double mean = g_S[f] / (double)NE;
    double var  = g_S[HF + f] / (double)NE - mean * mean;
    float istd = (float)rsqrt(var + 1e-5);
    float sc = g1[layer * HF + f] * istd;
    g_AF[f] = sc;
    g_AF[HF + f] = be1[layer * HF + f] - (float)mean * sc;
}

// ---------------- edge pass 2: segment reduction (no atomics) ---------------
__global__ __launch_bounds__(256) void k_edge2() {
    int t = threadIdx.x;
    int n = blockIdx.x * 4 + (t >> 6);
    int f = t & 63;
    if (n >= NN) return;
    float sc_a = g_AF[f],      sh_a = g_AF[HF + f];
    float sc_b = g_AF[64 + f], sh_b = g_AF[HF + 64 + f];
    int st = g_START[n], dg = g_DEG[n];
    float sum = 0.f;
    const __half2* zp = g_Zh + (size_t)st * 64 + f;
    #pragma unroll 4
    for (int q = 0; q < dg; q++) {
        __half2 h = zp[(size_t)q * 64];
        float a = __low2float(h)  * sc_a + sh_a;
        float b = __high2float(h) * sc_b + sh_b;
        sum += sig_f(a) * sp_f(b);
    }
    g_ACC[(size_t)n * NF + f] = sum / (float)max(dg, 1);
}

// ---------------- node BN stats + apply ----------------
__global__ void k_nstats() {
    __shared__ float s1[NF], s2[NF];
    int tid = threadIdx.x;
    if (tid < NF) { s1[tid] = 0.f; s2[tid] = 0.f; }
    __syncthreads();
    float a1 = 0.f, a2 = 0.f;
    int f = tid & 63;
    for (int i = blockIdx.x * 256 + tid; i < NN * NF; i += gridDim.x * 256) {
        float nm = g_ACC[i];
        a1 += nm; a2 += nm * nm;
    }
    atomicAdd(&s1[f], a1); atomicAdd(&s2[f], a2);
    __syncthreads();
    if (tid < NF) {
        atomicAdd(&g_NS[tid], (double)s1[tid]);
        atomicAdd(&g_NS[NF + tid], (double)s2[tid]);
    }
}

__global__ void k_nfin(const float* __restrict__ g2, const float* __restrict__ be2, int layer) {
    int f = threadIdx.x;  // 64
    double mean = g_NS[f] / (double)NN;
    double var  = g_NS[NF + f] / (double)NN - mean * mean;
    float istd = (float)rsqrt(var + 1e-5);
    float sc = g2[layer * NF + f] * istd;
    g_NAF[f] = sc;
    g_NAF[NF + f] = be2[layer * NF + f] - (float)mean * sc;
}

__global__ void k_napply() {
    for (int i = blockIdx.x * 256 + threadIdx.x; i < NN * NF; i += gridDim.x * 256) {
        int f = i & 63;
        float v = g_X[i] + g_ACC[i] * g_NAF[f] + g_NAF[NF + f];
        g_X[i] = sp_f(v);
    }
}

// ---------------- readout ----------------
__global__ void k_cryacc(const int* __restrict__ idx3) {
    int i = blockIdx.x * 256 + threadIdx.x;   // NN*NF exactly
    int n = i >> 6, f = i & 63;
    atomicAdd(&g_CRY[idx3[n] * NF + f], g_X[i]);
}

__global__ void k_head(const float* __restrict__ Wc, const float* __restrict__ bc,
                       const float* __restrict__ Wo, const float* __restrict__ bo,
                       float* __restrict__ out) {
    __shared__ float c[NF];
    __shared__ float r0s[4], r1s[4];
    int cid = blockIdx.x, tid = threadIdx.x;   // 128 threads
    if (tid < NF) {
        int cnt = g_CNT[cid];
        c[tid] = g_CRY[cid * NF + tid] / (float)max(cnt, 1);
    }
    __syncthreads();
    float acc = bc[tid];
    #pragma unroll
    for (int k = 0; k < NF; k++) acc += c[k] * Wc[k * HF + tid];
    float h = sp_f(acc);
    float o0 = h * Wo[tid * 2], o1 = h * Wo[tid * 2 + 1];
    #pragma unroll
    for (int s = 16; s; s >>= 1) {
        o0 += __shfl_down_sync(0xffffffffu, o0, s);
        o1 += __shfl_down_sync(0xffffffffu, o1, s);
    }
    if ((tid & 31) == 0) { r0s[tid >> 5] = o0; r1s[tid >> 5] = o1; }
    __syncthreads();
    if (tid == 0) {
        out[cid * 2]     = r0s[0] + r0s[1] + r0s[2] + r0s[3] + bo[0];
        out[cid * 2 + 1] = r1s[0] + r1s[1] + r1s[2] + r1s[3] + bo[1];
    }
}

// ---------------- launch ----------------
extern "C" void kernel_launch(void* const* d_in, const int* in_sizes, int n_in,
                              void* d_out, int out_size) {
    const int*   node_fea = (const int*)  d_in[0];
    const float* edge_fea = (const float*)d_in[1];
    const int*   idx1     = (const int*)  d_in[2];
    const int*   idx2     = (const int*)  d_in[3];
    const int*   idx3     = (const int*)  d_in[4];
    const float* emb      = (const float*)d_in[5];
    const float* Wf       = (const float*)d_in[6];
    const float* bf       = (const float*)d_in[7];
    const float* g1       = (const float*)d_in[8];
    const float* be1      = (const float*)d_in[9];
    const float* g2       = (const float*)d_in[10];
    const float* be2      = (const float*)d_in[11];
    const float* Wc       = (const float*)d_in[12];
    const float* bc       = (const float*)d_in[13];
    const float* Wo       = (const float*)d_in[14];
    const float* bo       = (const float*)d_in[15];
    float* out = (float*)d_out;

    k_pre<<<500, 256>>>();
    k_embed<<<6250, 256>>>(node_fea, emb);
    k_deg<<<6250, 256>>>(idx1);
    k_cnt3<<<391, 256>>>(idx3);
    k_scan1<<<391, 256>>>();
    k_scan2<<<1, 512>>>();
    k_scan3<<<391, 256>>>();
    k_perm<<<6250, 256>>>(idx1);
    for (int l = 0; l < 3; l++) {
        k_zstat<<<1, 256>>>();
        dim3 gg(1563, 2);
        k_nodegemm<<<gg, 256>>>(Wf, l);
        k_edge1<<<12500, 256>>>(edge_fea, idx1, idx2, Wf, bf, l);
        k_efin<<<1, 128>>>(g1, be1, l);
        k_edge2<<<25000, 256>>>();
        k_nstats<<<1024, 256>>>();
        k_nfin<<<1, 64>>>(g2, be2, l);
        k_napply<<<2048, 256>>>();
    }
    k_cryacc<<<25000, 256>>>(idx3);
    k_head<<<2000, 128>>>(Wc, bc, Wo, bo, out);
}

// round 4
// speedup vs baseline: 1.2758x; 1.2141x over previous
#include <cuda_runtime.h>
#include <cuda_fp16.h>
#include <math.h>

#define NN 100000
#define NE 1600000
#define NC 2000
#define NF 64
#define EFD 41
#define HF 128
#define DIN 169

typedef unsigned long long ull;

// ---------------- scratch (static __device__, no allocations) ----------------
__device__ float   g_X[NN * NF];           // node features
__device__ __half  g_P1h[NN * HF];         // X @ Wf[0:64]   (fp16)  25.6MB
__device__ __half  g_P2h[NN * HF];         // X @ Wf[64:128] (fp16)  25.6MB
__device__ __half2 g_Zh[(size_t)NE * 64];  // z pre-BN packed (gate,conv) 409.6MB
__device__ float   g_EFS[(size_t)NE * EFD];// edge features in sorted order 262.4MB
__device__ int     g_I1S[NE], g_I2S[NE];   // endpoints in sorted order
__device__ float   g_ACC[NN * NF];         // per-node msg means
__device__ int     g_DEG[NN];
__device__ int     g_CNT[NC];
__device__ float   g_CRY[NC * NF];
__device__ double  g_S[2 * HF];            // edge BN sum / sumsq
__device__ double  g_NS[2 * NF];           // node BN sum / sumsq
__device__ float   g_AF[2 * HF];           // edge BN scale/shift
__device__ float   g_NAF[2 * NF];          // node BN scale/shift
// counting-sort infra
__device__ int g_TMP[NN];
__device__ int g_BS[512];
__device__ int g_BSX[512];
__device__ int g_START[NN];
__device__ int g_CUR[NN];
__device__ int g_ESRC[NE];

// ---------------- helpers ----------------
__device__ __forceinline__ ull pack2(float x) {
    ull r; asm("mov.b64 %0, {%1, %1};" : "=l"(r) : "f"(x)); return r;
}
__device__ __forceinline__ ull packf2(float x, float y) {
    ull r; asm("mov.b64 %0, {%1, %2};" : "=l"(r) : "f"(x), "f"(y)); return r;
}
__device__ __forceinline__ void ffma2(ull& d, ull a, ull b) {
    asm("fma.rn.f32x2 %0, %1, %2, %0;" : "+l"(d) : "l"(a), "l"(b));
}
__device__ __forceinline__ float2 unpk(ull v) {
    float2 r; asm("mov.b64 {%0, %1}, %2;" : "=f"(r.x), "=f"(r.y) : "l"(v)); return r;
}
__device__ __forceinline__ float sp_f(float x) {
    return fmaxf(x, 0.f) + __logf(1.f + __expf(-fabsf(x)));
}
__device__ __forceinline__ float sig_f(float x) {
    return __fdividef(1.f, 1.f + __expf(-x));
}
__device__ __forceinline__ float2 h2f(unsigned u) {
    __half2 h = *(__half2*)&u; return __half22float2(h);
}

// ---------------- setup kernels ----------------
__global__ void k_pre() {
    int i = blockIdx.x * 256 + threadIdx.x;
    if (i < NN) g_DEG[i] = 0;
    if (i < NC) g_CNT[i] = 0;
    if (i < NC * NF) g_CRY[i] = 0.f;
}

__global__ void k_embed(const int* __restrict__ nf, const float* __restrict__ emb) {
    int i = blockIdx.x * 256 + threadIdx.x;       // NN*16
    if (i >= NN * 16) return;
    int n = i >> 4, c = i & 15;
    int v = nf[n];
    float4 val = ((const float4*)(emb + (size_t)v * NF))[c];
    ((float4*)(g_X + (size_t)n * NF))[c] = val;
}

__global__ void k_deg(const int* __restrict__ idx1) {
    int e = blockIdx.x * 256 + threadIdx.x;
    if (e < NE) atomicAdd(&g_DEG[idx1[e]], 1);
}

__global__ void k_cnt3(const int* __restrict__ idx3) {
    int n = blockIdx.x * 256 + threadIdx.x;
    if (n < NN) atomicAdd(&g_CNT[idx3[n]], 1);
}

// ---------------- counting sort ----------------
__global__ void k_scan1() {
    __shared__ int s[256];
    int tid = threadIdx.x;
    int n = blockIdx.x * 256 + tid;
    int d = (n < NN) ? g_DEG[n] : 0;
    s[tid] = d;
    __syncthreads();
    for (int off = 1; off < 256; off <<= 1) {
        int v = (tid >= off) ? s[tid - off] : 0;
        __syncthreads();
        s[tid] += v;
        __syncthreads();
    }
    if (n < NN) g_TMP[n] = s[tid] - d;
    if (tid == 255) g_BS[blockIdx.x] = s[255];
}

__global__ void k_scan2() {
    __shared__ int s[512];
    int tid = threadIdx.x;
    int d = (tid < 391) ? g_BS[tid] : 0;
    s[tid] = d;
    __syncthreads();
    for (int off = 1; off < 512; off <<= 1) {
        int v = (tid >= off) ? s[tid - off] : 0;
        __syncthreads();
        s[tid] += v;
        __syncthreads();
    }
    if (tid < 391) g_BSX[tid] = s[tid] - d;
}

__global__ void k_scan3() {
    int n = blockIdx.x * 256 + threadIdx.x;
    if (n < NN) {
        int st = g_TMP[n] + g_BSX[blockIdx.x];
        g_START[n] = st;
        g_CUR[n] = st;
    }
}

__global__ void k_perm(const int* __restrict__ idx1) {
    int e = blockIdx.x * 256 + threadIdx.x;
    if (e < NE) {
        int pos = atomicAdd(&g_CUR[idx1[e]], 1);
        g_ESRC[pos] = e;
    }
}

// permute edge data into sorted order (one-time)
__global__ void k_permidx(const int* __restrict__ idx1, const int* __restrict__ idx2) {
    int p = blockIdx.x * 256 + threadIdx.x;
    if (p < NE) {
        int e = g_ESRC[p];
        g_I1S[p] = idx1[e];
        g_I2S[p] = idx2[e];
    }
}

__global__ void k_permef(const float* __restrict__ ef) {
    size_t i = (size_t)blockIdx.x * 256 + threadIdx.x;   // NE*EFD total
    if (i >= (size_t)NE * EFD) return;
    int p = (int)(i / EFD), c = (int)(i - (size_t)p * EFD);
    g_EFS[i] = __ldg(ef + (size_t)g_ESRC[p] * EFD + c);
}

__global__ void k_zstat() {
    int tid = threadIdx.x;  // 256
    g_S[tid] = 0.0;
    if (tid < 2 * NF) g_NS[tid] = 0.0;
}

// ---------------- node GEMM: P1/P2(half) = X @ Wf[l][half*64 : +64] --------
__global__ __launch_bounds__(256) void k_nodegemm(const float* __restrict__ Wf, int layer) {
    __shared__ float sW[64 * HF];   // 32 KB
    __shared__ float sX[64 * NF];   // 16 KB
    const float* Wb = Wf + ((size_t)layer * DIN + blockIdx.y * 64) * HF;
    int tid = threadIdx.x;
    #pragma unroll 4
    for (int i = tid; i < 64 * HF; i += 256) sW[i] = Wb[i];
    int n0 = blockIdx.x * 64;
    for (int i = tid; i < 64 * NF; i += 256) {
        int r = i >> 6, c = i & 63, n = n0 + r;
        sX[i] = (n < NN) ? g_X[(size_t)n * NF + c] : 0.f;
    }
    __syncthreads();
    int fg = tid & 15, eg = tid >> 4;
    int fa = fg * 4, fb = 64 + fg * 4;
    ull acc[4][4];
    #pragma unroll
    for (int j = 0; j < 4; j++)
        #pragma unroll
        for (int q = 0; q < 4; q++) acc[j][q] = 0ULL;
    #pragma unroll 1
    for (int k = 0; k < 64; k++) {
        ulonglong2 wa = *(const ulonglong2*)(sW + k * HF + fa);
        ulonglong2 wb = *(const ulonglong2*)(sW + k * HF + fb);
        #pragma unroll
        for (int j = 0; j < 4; j++) {
            ull a = pack2(sX[(eg * 4 + j) * NF + k]);
            ffma2(acc[j][0], a, wa.x); ffma2(acc[j][1], a, wa.y);
            ffma2(acc[j][2], a, wb.x); ffma2(acc[j][3], a, wb.y);
        }
    }
    __half* out = blockIdx.y ? g_P2h : g_P1h;
    #pragma unroll
    for (int j = 0; j < 4; j++) {
        int n = n0 + eg * 4 + j;
        if (n < NN) {
            float2 v0 = unpk(acc[j][0]), v1 = unpk(acc[j][1]);
            float2 v2 = unpk(acc[j][2]), v3 = unpk(acc[j][3]);
            __half2 ha[2], hb[2];
            ha[0] = __floats2half2_rn(v0.x, v0.y);
            ha[1] = __floats2half2_rn(v1.x, v1.y);
            hb[0] = __floats2half2_rn(v2.x, v2.y);
            hb[1] = __floats2half2_rn(v3.x, v3.y);
            *(uint2*)(out + (size_t)n * HF + fa) = *(uint2*)ha;
            *(uint2*)(out + (size_t)n * HF + fb) = *(uint2*)hb;
        }
    }
}

// ---------------- edge pass 1 (sorted): z -> Zh (fp16) + BN stats -----------
__global__ __launch_bounds__(256) void k_edge1(
    const float* __restrict__ Wf, const float* __restrict__ bfp, int layer)
{
    __shared__ float sW[42 * HF];      // 21 KB (row 41 zeroed)
    __shared__ float sE[128 * 42];     // 21 KB (col 41 zeroed)
    __shared__ int sI1[128], sI2[128];
    __shared__ float sS1[HF], sS2[HF];
    const float* Wb = Wf + ((size_t)layer * DIN + 128) * HF;
    int tid = threadIdx.x;
    for (int i = tid; i < 42 * HF; i += 256) sW[i] = (i < EFD * HF) ? Wb[i] : 0.f;
    size_t p0 = (size_t)blockIdx.x * 128;
    if (tid < 128) {
        sI1[tid] = g_I1S[p0 + tid];
        sI2[tid] = g_I2S[p0 + tid];
    }
    if (tid < HF) { sS1[tid] = 0.f; sS2[tid] = 0.f; }
    // coalesced streaming load of sorted edge features
    {
        const float* efb = g_EFS + p0 * EFD;
        for (int i = tid; i < 128 * 42; i += 256) {
            int r = i / 42, c = i - r * 42;
            sE[i] = (c < EFD) ? __ldcs(efb + r * EFD + c) : 0.f;
        }
    }
    __syncthreads();

    int fg = tid & 15, eg = tid >> 4;
    int fa = fg * 4, fb = 64 + fg * 4;
    const float* bfl = bfp + layer * HF;
    float4 bva = *(const float4*)(bfl + fa);
    float4 bvb = *(const float4*)(bfl + fb);

    ull acc[8][4];
    #pragma unroll
    for (int j = 0; j < 8; j++) {
        int r = eg * 8 + j;
        int i1 = sI1[r], i2 = sI2[r];
        uint2 u1a = *(const uint2*)(g_P1h + (size_t)i1 * HF + fa);
        uint2 u1b = *(const uint2*)(g_P1h + (size_t)i1 * HF + fb);
        uint2 u2a = *(const uint2*)(g_P2h + (size_t)i2 * HF + fa);
        uint2 u2b = *(const uint2*)(g_P2h + (size_t)i2 * HF + fb);
        float2 p1a0 = h2f(u1a.x), p1a1 = h2f(u1a.y);
        float2 p1b0 = h2f(u1b.x), p1b1 = h2f(u1b.y);
        float2 p2a0 = h2f(u2a.x), p2a1 = h2f(u2a.y);
        float2 p2b0 = h2f(u2b.x), p2b1 = h2f(u2b.y);
        acc[j][0] = packf2(p1a0.x + p2a0.x + bva.x, p1a0.y + p2a0.y + bva.y);
        acc[j][1] = packf2(p1a1.x + p2a1.x + bva.z, p1a1.y + p2a1.y + bva.w);
        acc[j][2] = packf2(p1b0.x + p2b0.x + bvb.x, p1b0.y + p2b0.y + bvb.y);
        acc[j][3] = packf2(p1b1.x + p2b1.x + bvb.z, p1b1.y + p2b1.y + bvb.w);
    }

    #pragma unroll 1
    for (int k = 0; k < 42; k += 2) {
        ulonglong2 wa0 = *(const ulonglong2*)(sW + k * HF + fa);
        ulonglong2 wb0 = *(const ulonglong2*)(sW + k * HF + fb);
        ulonglong2 wa1 = *(const ulonglong2*)(sW + (k + 1) * HF + fa);
        ulonglong2 wb1 = *(const ulonglong2*)(sW + (k + 1) * HF + fb);
        #pragma unroll
        for (int j = 0; j < 8; j++) {
            float2 av = *(const float2*)(sE + (eg * 8 + j) * 42 + k);
            ull a0 = pack2(av.x), a1 = pack2(av.y);
            ffma2(acc[j][0], a0, wa0.x); ffma2(acc[j][1], a0, wa0.y);
            ffma2(acc[j][2], a0, wb0.x); ffma2(acc[j][3], a0, wb0.y);
            ffma2(acc[j][0], a1, wa1.x); ffma2(acc[j][1], a1, wa1.y);
            ffma2(acc[j][2], a1, wb1.x); ffma2(acc[j][3], a1, wb1.y);
        }
    }

    float s1[8] = {0,0,0,0,0,0,0,0}, s2[8] = {0,0,0,0,0,0,0,0};
    #pragma unroll
    for (int j = 0; j < 8; j++) {
        size_t p = p0 + eg * 8 + j;
        float2 v0 = unpk(acc[j][0]), v1 = unpk(acc[j][1]);
        float2 v2 = unpk(acc[j][2]), v3 = unpk(acc[j][3]);
        __half2 hp[4];
        hp[0] = __floats2half2_rn(v0.x, v2.x);
        hp[1] = __floats2half2_rn(v0.y, v2.y);
        hp[2] = __floats2half2_rn(v1.x, v3.x);
        hp[3] = __floats2half2_rn(v1.y, v3.y);
        __stcs((uint4*)(g_Zh + p * 64 + fa), *(uint4*)hp);   // streaming store
        s1[0] += v0.x; s2[0] += v0.x * v0.x;
        s1[1] += v0.y; s2[1] += v0.y * v0.y;
        s1[2] += v1.x; s2[2] += v1.x * v1.x;
        s1[3] += v1.y; s2[3] += v1.y * v1.y;
        s1[4] += v2.x; s2[4] += v2.x * v2.x;
        s1[5] += v2.y; s2[5] += v2.y * v2.y;
        s1[6] += v3.x; s2[6] += v3.x * v3.x;
        s1[7] += v3.y; s2[7] += v3.y * v3.y;
    }
    #pragma unroll
    for (int q = 0; q < 4; q++) {
        atomicAdd(&sS1[fa + q], s1[q]);     atomicAdd(&sS2[fa + q], s2[q]);
        atomicAdd(&sS1[fb + q], s1[4 + q]); atomicAdd(&sS2[fb + q], s2[4 + q]);
    }
    __syncthreads();
    if (tid < HF) {
        atomicAdd(&g_S[tid], (double)sS1[tid]);
        atomicAdd(&g_S[HF + tid], (double)sS2[tid]);
    }
}

__global__ void k_efin(const float* __restrict__ g1, const float* __restrict__ be1, int layer) {
    int f = threadIdx.x;  // 128
    double mean = g_S[f] / (double)NE;
    double var  = g_S[HF + f] / (double)NE - mean * mean;
    float istd = (float)rsqrt(var + 1e-5);
    float sc = g1[layer * HF + f] * istd;
    g_AF[f] = sc;
    g_AF[HF + f] = be1[layer * HF + f] - (float)mean * sc;
}

// ---------------- edge pass 2: segment reduction (no atomics) ---------------
__global__ __launch_bounds__(256) void k_edge2() {
    int t = threadIdx.x;
    int n = blockIdx.x * 4 + (t >> 6);
    int f = t & 63;
    if (n >= NN) return;
    float sc_a = g_AF[f],      sh_a = g_AF[HF + f];
    float sc_b = g_AF[64 + f], sh_b = g_AF[HF + 64 + f];
    int st = g_START[n], dg = g_DEG[n];
    float sum = 0.f;
    const unsigned* zp = (const unsigned*)(g_Zh + (size_t)st * 64 + f);
    #pragma unroll 4
    for (int q = 0; q < dg; q++) {
        unsigned u = __ldcs(zp + (size_t)q * 64);
        float2 v = h2f(u);
        float a = v.x * sc_a + sh_a;
        float b = v.y * sc_b + sh_b;
        sum += sig_f(a) * sp_f(b);
    }
    g_ACC[(size_t)n * NF + f] = sum / (float)max(dg, 1);
}

// ---------------- node BN stats + apply ----------------
__global__ void k_nstats() {
    __shared__ float s1[NF], s2[NF];
    int tid = threadIdx.x;
    if (tid < NF) { s1[tid] = 0.f; s2[tid] = 0.f; }
    __syncthreads();
    float a1 = 0.f, a2 = 0.f;
    int f = tid & 63;
    for (int i = blockIdx.x * 256 + tid; i < NN * NF; i += gridDim.x * 256) {
        float nm = g_ACC[i];
        a1 += nm; a2 += nm * nm;
    }
    atomicAdd(&s1[f], a1); atomicAdd(&s2[f], a2);
    __syncthreads();
    if (tid < NF) {
        atomicAdd(&g_NS[tid], (double)s1[tid]);
        atomicAdd(&g_NS[NF + tid], (double)s2[tid]);
    }
}

__global__ void k_nfin(const float* __restrict__ g2, const float* __restrict__ be2, int layer) {
    int f = threadIdx.x;  // 64
    double mean = g_NS[f] / (double)NN;
    double var  = g_NS[NF + f] / (double)NN - mean * mean;
    float istd = (float)rsqrt(var + 1e-5);
    float sc = g2[layer * NF + f] * istd;
    g_NAF[f] = sc;
    g_NAF[NF + f] = be2[layer * NF + f] - (float)mean * sc;
}

__global__ void k_napply() {
    for (int i = blockIdx.x * 256 + threadIdx.x; i < NN * NF; i += gridDim.x * 256) {
        int f = i & 63;
        float v = g_X[i] + g_ACC[i] * g_NAF[f] + g_NAF[NF + f];
        g_X[i] = sp_f(v);
    }
}

// ---------------- readout ----------------
__global__ void k_cryacc(const int* __restrict__ idx3) {
    int i = blockIdx.x * 256 + threadIdx.x;   // NN*NF
    int n = i >> 6, f = i & 63;
    atomicAdd(&g_CRY[idx3[n] * NF + f], g_X[i]);
}

__global__ void k_head(const float* __restrict__ Wc, const float* __restrict__ bc,
                       const float* __restrict__ Wo, const float* __restrict__ bo,
                       float* __restrict__ out) {
    __shared__ float c[NF];
    __shared__ float r0s[4], r1s[4];
    int cid = blockIdx.x, tid = threadIdx.x;   // 128 threads
    if (tid < NF) {
        int cnt = g_CNT[cid];
        c[tid] = g_CRY[cid * NF + tid] / (float)max(cnt, 1);
    }
    __syncthreads();
    float acc = bc[tid];
    #pragma unroll
    for (int k = 0; k < NF; k++) acc += c[k] * Wc[k * HF + tid];
    float h = sp_f(acc);
    float o0 = h * Wo[tid * 2], o1 = h * Wo[tid * 2 + 1];
    #pragma unroll
    for (int s = 16; s; s >>= 1) {
        o0 += __shfl_down_sync(0xffffffffu, o0, s);
        o1 += __shfl_down_sync(0xffffffffu, o1, s);
    }
    if ((tid & 31) == 0) { r0s[tid >> 5] = o0; r1s[tid >> 5] = o1; }
    __syncthreads();
    if (tid == 0) {
        out[cid * 2]     = r0s[0] + r0s[1] + r0s[2] + r0s[3] + bo[0];
        out[cid * 2 + 1] = r1s[0] + r1s[1] + r1s[2] + r1s[3] + bo[1];
    }
}

// ---------------- launch ----------------
extern "C" void kernel_launch(void* const* d_in, const int* in_sizes, int n_in,
                              void* d_out, int out_size) {
    const int*   node_fea = (const int*)  d_in[0];
    const float* edge_fea = (const float*)d_in[1];
    const int*   idx1     = (const int*)  d_in[2];
    const int*   idx2     = (const int*)  d_in[3];
    const int*   idx3     = (const int*)  d_in[4];
    const float* emb      = (const float*)d_in[5];
    const float* Wf       = (const float*)d_in[6];
    const float* bf       = (const float*)d_in[7];
    const float* g1       = (const float*)d_in[8];
    const float* be1      = (const float*)d_in[9];
    const float* g2       = (const float*)d_in[10];
    const float* be2      = (const float*)d_in[11];
    const float* Wc       = (const float*)d_in[12];
    const float* bc       = (const float*)d_in[13];
    const float* Wo       = (const float*)d_in[14];
    const float* bo       = (const float*)d_in[15];
    float* out = (float*)d_out;

    k_pre<<<500, 256>>>();
    k_embed<<<6250, 256>>>(node_fea, emb);
    k_deg<<<6250, 256>>>(idx1);
    k_cnt3<<<391, 256>>>(idx3);
    k_scan1<<<391, 256>>>();
    k_scan2<<<1, 512>>>();
    k_scan3<<<391, 256>>>();
    k_perm<<<6250, 256>>>(idx1);
    k_permidx<<<6250, 256>>>(idx1, idx2);
    {
        size_t tot = (size_t)NE * EFD;
        int blocks = (int)((tot + 255) / 256);
        k_permef<<<blocks, 256>>>(edge_fea);
    }
    for (int l = 0; l < 3; l++) {
        k_zstat<<<1, 256>>>();
        dim3 gg(1563, 2);
        k_nodegemm<<<gg, 256>>>(Wf, l);
        k_edge1<<<12500, 256>>>(Wf, bf, l);
        k_efin<<<1, 128>>>(g1, be1, l);
        k_edge2<<<25000, 256>>>();
        k_nstats<<<1024, 256>>>();
        k_nfin<<<1, 64>>>(g2, be2, l);
        k_napply<<<2048, 256>>>();
    }
    k_cryacc<<<25000, 256>>>(idx3);
    k_head<<<2000, 128>>>(Wc, bc, Wo, bo, out);
}